// round 6
// baseline (speedup 1.0000x reference)
#include <cuda_runtime.h>
#include <cuda_fp16.h>
#include <math.h>

#define BATCH 4
#define NPT   1024
#define HID   64
#define HEADS 16
#define NB    512
#define TPB   512
#define GRID  296
#define ROWQ  7            // float4 quarters per LUT row (112 B pitch; 96 B used)

// Single fused kernel. Every block:
//   phase 1: max ||c||^2 over all points (associative max -> identical result per block)
//   phase 2: build LUT in smem: per bin, 16 fp32 node values + 16 fp16 slopes
//   phase 3: process contiguous rows; thread owns 2 consecutive j; float2 stores per head.
__global__ __launch_bounds__(TPB, 2)
void k_fused(const float* __restrict__ coords,
             const float* __restrict__ w1, const float* __restrict__ b1,
             const float* __restrict__ w2, const float* __restrict__ b2,
             float* __restrict__ out) {
    extern __shared__ float smem[];                  // (NB+1)*ROWQ*4 floats + 32 red
    float4* lut4 = (float4*)smem;
    float*  red  = smem + (NB + 1) * ROWQ * 4;

    const int tid = threadIdx.x;

    // ---------- phase 1: range ----------
    float mx = 0.0f;
    for (int idx = tid; idx < BATCH * NPT; idx += TPB) {
        float x = coords[idx * 3 + 0];
        float y = coords[idx * 3 + 1];
        float z = coords[idx * 3 + 2];
        mx = fmaxf(mx, fmaf(x, x, fmaf(y, y, z * z)));
    }
    #pragma unroll
    for (int s = 16; s; s >>= 1) mx = fmaxf(mx, __shfl_xor_sync(0xFFFFFFFFu, mx, s));
    if ((tid & 31) == 0) red[tid >> 5] = mx;
    __syncthreads();
    if (tid == 0) {
        float m = red[0];
        #pragma unroll
        for (int w = 1; w < TPB / 32; w++) m = fmaxf(m, red[w]);
        float range = fmaxf(2.0f * sqrtf(m) * 1.0002f, 1e-6f);
        red[16] = (float)NB / range;       // invh
        red[17] = range / (float)NB;       // h
    }
    __syncthreads();
    const float invh  = red[16];
    const float hstep = red[17];

    // ---------- phase 2a: node values (fp32) ----------
    for (int n = tid; n <= NB; n += TPB) {
        float d = hstep * (float)n;
        float acc[HEADS];
        #pragma unroll
        for (int k = 0; k < HEADS; k++) acc[k] = __ldg(&b2[k]);
        #pragma unroll 4
        for (int hh = 0; hh < HID; hh++) {
            float z = fmaf(d, __ldg(&w1[hh]), __ldg(&b1[hh]));
            float s = z / (1.0f + expf(-z));                // silu
            #pragma unroll
            for (int k = 0; k < HEADS; k++) acc[k] = fmaf(s, __ldg(&w2[hh * HEADS + k]), acc[k]);
        }
        // values: chunk c (c=0,1) -> quarters 3c, 3c+1 hold heads 8c..8c+7
        float* row = smem + n * ROWQ * 4;
        #pragma unroll
        for (int c = 0; c < 2; c++) {
            float4 v0 = make_float4(acc[8*c+0], acc[8*c+1], acc[8*c+2], acc[8*c+3]);
            float4 v1 = make_float4(acc[8*c+4], acc[8*c+5], acc[8*c+6], acc[8*c+7]);
            ((float4*)row)[3*c]     = v0;
            ((float4*)row)[3*c + 1] = v1;
        }
    }
    __syncthreads();

    // ---------- phase 2b: fp16 slopes into quarter 3c+2 ----------
    for (int n = tid; n < NB; n += TPB) {
        const float* rA = smem + n * ROWQ * 4;
        const float* rN = rA + ROWQ * 4;
        #pragma unroll
        for (int c = 0; c < 2; c++) {
            __half2 s[4];
            #pragma unroll
            for (int m = 0; m < 4; m++) {
                int k = 8 * c + 2 * m;
                // value layout inside chunk: quarter 3c has heads 8c..+3, 3c+1 has +4..+7
                float a0 = rA[(3*c) * 4 + ((2*m)   & 3) + ((2*m)   >> 2) * 4];
                float a1 = rA[(3*c) * 4 + ((2*m+1) & 3) + ((2*m+1) >> 2) * 4];
                float n0 = rN[(3*c) * 4 + ((2*m)   & 3) + ((2*m)   >> 2) * 4];
                float n1 = rN[(3*c) * 4 + ((2*m+1) & 3) + ((2*m+1) >> 2) * 4];
                (void)k;
                s[m] = __floats2half2_rn(n0 - a0, n1 - a1);
            }
            float4 sq;
            memcpy(&sq, s, 16);
            ((float4*)(smem + n * ROWQ * 4))[3*c + 2] = sq;
        }
    }
    __syncthreads();

    // ---------- phase 3: main pair loop ----------
    const int q  = tid;                 // j-pair index 0..511
    const int j0 = q << 1;
    const size_t NN2 = (size_t)NPT * NPT / 2;

    const int nrow = BATCH * NPT;       // 4096
    int per = nrow / gridDim.x, rem = nrow % gridDim.x;
    int start, cnt;
    if ((int)blockIdx.x < rem) { cnt = per + 1; start = blockIdx.x * cnt; }
    else                       { cnt = per;     start = rem * (per + 1) + (blockIdx.x - rem) * per; }

    int bcur = -1;
    float cj0x=0, cj0y=0, cj0z=0, cj1x=0, cj1y=0, cj1z=0;

    for (int row = start; row < start + cnt; row++) {
        int b = row >> 10, i = row & 1023;
        if (b != bcur) {
            bcur = b;
            const float* cb = coords + ((size_t)b * NPT + j0) * 3;
            cj0x = cb[0]; cj0y = cb[1]; cj0z = cb[2];
            cj1x = cb[3]; cj1y = cb[4]; cj1z = cb[5];
        }
        const float* cip = coords + ((size_t)b * NPT + i) * 3;
        float cix = __ldg(cip), ciy = __ldg(cip + 1), ciz = __ldg(cip + 2);

        float t0, t1; int a0, a1;
        {
            float dx = cix - cj0x, dy = ciy - cj0y, dz = ciz - cj0z;
            float x  = sqrtf(fmaf(dx, dx, fmaf(dy, dy, dz * dz))) * invh;
            int bin  = min((int)x, NB - 1);
            t0 = x - (float)bin; a0 = bin * ROWQ;
        }
        {
            float dx = cix - cj1x, dy = ciy - cj1y, dz = ciz - cj1z;
            float x  = sqrtf(fmaf(dx, dx, fmaf(dy, dy, dz * dz))) * invh;
            int bin  = min((int)x, NB - 1);
            t1 = x - (float)bin; a1 = bin * ROWQ;
        }

        float2* po = (float2*)out + (size_t)b * HEADS * NN2 + (size_t)i * (NPT / 2) + q;
        #pragma unroll
        for (int c = 0; c < 2; c++) {
            float4 vA0 = lut4[a0 + 3*c], vA1 = lut4[a0 + 3*c + 1], sA = lut4[a0 + 3*c + 2];
            float4 vB0 = lut4[a1 + 3*c], vB1 = lut4[a1 + 3*c + 1], sB = lut4[a1 + 3*c + 2];
            const __half2* hA = (const __half2*)&sA;
            const __half2* hB = (const __half2*)&sB;
            const float* fA0 = (const float*)&vA0;
            const float* fA1 = (const float*)&vA1;
            const float* fB0 = (const float*)&vB0;
            const float* fB1 = (const float*)&vB1;
            #pragma unroll
            for (int m = 0; m < 4; m++) {
                float2 sa = __half22float2(hA[m]);
                float2 sb = __half22float2(hB[m]);
                int k0 = 2 * m;                       // heads 8c+k0, 8c+k0+1
                float va0 = (k0 < 4)     ? fA0[k0]       : fA1[k0 - 4];
                float va1 = (k0+1 < 4)   ? fA0[k0 + 1]   : fA1[k0 - 3];
                float vb0 = (k0 < 4)     ? fB0[k0]       : fB1[k0 - 4];
                float vb1 = (k0+1 < 4)   ? fB0[k0 + 1]   : fB1[k0 - 3];
                float2 r0, r1;
                r0.x = fmaf(t0, sa.x, va0); r0.y = fmaf(t1, sb.x, vb0);
                r1.x = fmaf(t0, sa.y, va1); r1.y = fmaf(t1, sb.y, vb1);
                po[(size_t)(8*c + k0)     * NN2] = r0;
                po[(size_t)(8*c + k0 + 1) * NN2] = r1;
            }
        }
    }
}

extern "C" void kernel_launch(void* const* d_in, const int* in_sizes, int n_in,
                              void* d_out, int out_size) {
    const float* coords = (const float*)d_in[0];
    const float* w1     = (const float*)d_in[1];
    const float* b1     = (const float*)d_in[2];
    const float* w2     = (const float*)d_in[3];
    const float* b2     = (const float*)d_in[4];
    float* out = (float*)d_out;

    const int smem_bytes = ((NB + 1) * ROWQ * 4 + 32) * (int)sizeof(float);  // ~57.6 KB
    cudaFuncSetAttribute(k_fused, cudaFuncAttributeMaxDynamicSharedMemorySize, smem_bytes);
    k_fused<<<GRID, TPB, smem_bytes>>>(coords, w1, b1, w2, b2, out);
}